// round 3
// baseline (speedup 1.0000x reference)
#include <cuda_runtime.h>
#include <math.h>
#include <stdint.h>

// ---------------- problem constants ----------------
#define BB    4
#define HH    32
#define KVH   8
#define DD    128
#define HID   4096
#define SC    8191          // cache length
#define SS    8192          // total sequence
#define WW    512           // blocks (S/BLK)
#define BLK   16
#define HIST  64
#define NSEL  64            // TOPK/BLK
#define MAXBL 80            // 64 topk + 8 forced, padded

#define KSPL  8             // k-splits for GEMVs
#define NCOL  (HID + 1024 + 1024)   // 6144 qkv columns

#define NSTRIP 8            // h-strips for conv
#define HSTR   8            // rows per strip

typedef unsigned long long ull;

// packed fp32x2 FMA (Blackwell): two exact IEEE fp32 FMAs per instruction
#define FMA_F32X2(d, a, b, c) \
    asm("fma.rn.f32x2 %0, %1, %2, %3;" : "=l"(d) : "l"(a), "l"(b), "l"(c))
#define UNPACK2(lo, hi, q) \
    asm("mov.b64 {%0, %1}, %2;" : "=f"(lo), "=f"(hi) : "l"(q))

// ---------------- device scratch ----------------
__device__ float g_part [KSPL * BB * NCOL];          // qkv gemv partials
__device__ float g_q    [BB * HH * DD];              // roped q
__device__ float g_kn   [BB * KVH * DD];             // roped new k
__device__ float g_vn   [BB * KVH * DD];             // new v
__device__ float g_cpart[NSTRIP * BB * HH * WW];     // conv strip partials
__device__ float g_tsp  [BB * HH * WW];              // cnn scores
__device__ int   g_blist[BB * HH * MAXBL];           // selected block lists
__device__ int   g_bcnt [BB * HH];
__device__ float g_ctx  [BB * HID];                  // attention output
__device__ float g_opart[KSPL * BB * HID];           // Wo gemv partials

// ================= QKV GEMV: partials =================
__global__ void k_qkv(const float* __restrict__ hid,
                      const float* __restrict__ Wq,
                      const float* __restrict__ Wk,
                      const float* __restrict__ Wv) {
    __shared__ float hs[BB][512];
    const int ks = blockIdx.y;
    const int k0 = ks * 512;
    for (int i = threadIdx.x; i < BB * 512; i += 256) {
        int b = i >> 9, kk = i & 511;
        hs[b][kk] = hid[b * HID + k0 + kk];
    }
    __syncthreads();

    const int c = blockIdx.x * 256 + threadIdx.x;   // 0..6143
    const float* Wm; int ld, cc;
    if (c < HID)              { Wm = Wq; ld = HID;  cc = c; }
    else if (c < HID + 1024)  { Wm = Wk; ld = 1024; cc = c - HID; }
    else                      { Wm = Wv; ld = 1024; cc = c - HID - 1024; }

    float a0 = 0.f, a1 = 0.f, a2 = 0.f, a3 = 0.f;
    const float* p = Wm + (size_t)k0 * ld + cc;
#pragma unroll 8
    for (int kk = 0; kk < 512; ++kk) {
        float w = p[(size_t)kk * ld];
        a0 = fmaf(hs[0][kk], w, a0);
        a1 = fmaf(hs[1][kk], w, a1);
        a2 = fmaf(hs[2][kk], w, a2);
        a3 = fmaf(hs[3][kk], w, a3);
    }
    g_part[((ks * BB + 0) * NCOL) + c] = a0;
    g_part[((ks * BB + 1) * NCOL) + c] = a1;
    g_part[((ks * BB + 2) * NCOL) + c] = a2;
    g_part[((ks * BB + 3) * NCOL) + c] = a3;
}

// ================= fused reduce + RoPE =================
__global__ void k_rope(const float* __restrict__ cosb, const float* __restrict__ sinb) {
    int i = blockIdx.x * 256 + threadIdx.x;      // < BB*NCOL
    if (i >= BB * NCOL) return;
    int b = i / NCOL, c = i - b * NCOL;
    float v = 0.f;
#pragma unroll
    for (int ks = 0; ks < KSPL; ++ks) v += g_part[(ks * BB + b) * NCOL + c];

    if (c < HID + 1024) {   // q or k : apply rope
        int d = c & (DD - 1);
        int pair = (d < DD / 2) ? c + DD / 2 : c - DD / 2;
        float pv = 0.f;
#pragma unroll
        for (int ks = 0; ks < KSPL; ++ks) pv += g_part[(ks * BB + b) * NCOL + pair];
        float cs = cosb[b * DD + d];
        float sn = sinb[b * DD + d];
        float rot = (d < DD / 2) ? -pv : pv;
        float out = v * cs + rot * sn;
        if (c < HID) g_q[b * HID + c] = out;
        else         g_kn[b * (KVH * DD) + (c - HID)] = out;
    } else {
        g_vn[b * (KVH * DD) + (c - HID - 1024)] = v;
    }
}

// ================= fused CNN, h-striped, pack-free f32x2 conv2 =================
// dynamic smem layout (floats):
//  y1d : 16*10*36*2 = 11520   (conv1 out, DUPLICATED pairs)
//  sx  : 12*36      = 432
//  w2s : 144*32     = 4608    (k-major, c2 contiguous)
//  w1s : 144, b1s 16, b2s 32, c3s 32
//  red : 32*32      = 1024
#define CONV_SMEM_FLOATS (11520 + 432 + 4608 + 144 + 16 + 32 + 32 + 1024)
#define CONV_SMEM_BYTES  (CONV_SMEM_FLOATS * 4)

__global__ void __launch_bounds__(256, 3)
k_conv(const float* __restrict__ hist,
       const float* __restrict__ c1w, const float* __restrict__ c1b,
       const float* __restrict__ c2w, const float* __restrict__ c2b,
       const float* __restrict__ c3w, const float* __restrict__ c3b) {
    extern __shared__ float sm[];
    float* y1d = sm;                    // [c1][sh 0..9][wi 0..35] x2 dup
    float* sx  = y1d + 11520;           // [12][36]
    float* w2s = sx  + 432;             // [144][32]
    float* w1s = w2s + 4608;
    float* b1s = w1s + 144;
    float* b2s = b1s + 16;
    float* c3s = b2s + 32;
    float* red = c3s + 32;

    const int n   = blockIdx.z;            // image 0..127
    const int h0  = blockIdx.y * HSTR;     // strip base row
    const int w0  = blockIdx.x * 32;       // w tile base
    const int tid = threadIdx.x;

    // ---- load weights ----
    for (int i = tid; i < 144; i += 256) w1s[i] = c1w[i];
    if (tid < 16) b1s[tid] = c1b[tid];
    if (tid < 32) { b2s[tid] = c2b[tid]; c3s[tid] = c3w[tid]; }
    for (int i = tid; i < 32 * 144; i += 256) {
        int c2 = i & 31, kk = i >> 5;
        int c1 = kk / 9, r = kk - c1 * 9;
        w2s[kk * 32 + c2] = c2w[(c2 * 16 + c1) * 9 + r];
    }
    // ---- load x strip with halo, zero padded ----
    const float* xim = hist + (size_t)n * HIST * WW;
    for (int i = tid; i < 12 * 36; i += 256) {
        int sh = i / 36, sw = i - sh * 36;
        int h = h0 - 2 + sh, w = w0 - 2 + sw;
        float v = 0.f;
        if ((unsigned)h < 64u && (unsigned)w < 512u) v = xim[h * WW + w];
        sx[i] = v;
    }
    __syncthreads();

    // ---- conv1: rows sh 0..9 (hh = h0-1+sh), wi 0..33; write duplicated ----
    for (int o = tid; o < 16 * 10 * 34; o += 256) {
        int c1 = o / 340;
        int r  = o - c1 * 340;
        int sh = r / 34;
        int wi = r - sh * 34;
        int hh = h0 - 1 + sh;
        int w  = w0 - 1 + wi;
        float v = 0.f;
        if ((unsigned)hh < 64u && (unsigned)w < 512u) {
            const float* wp = w1s + c1 * 9;
            float s = b1s[c1];
#pragma unroll
            for (int dh = 0; dh < 3; ++dh) {
                const float* xr = sx + (sh + dh) * 36 + wi;
                s = fmaf(wp[dh * 3 + 0], xr[0], s);
                s = fmaf(wp[dh * 3 + 1], xr[1], s);
                s = fmaf(wp[dh * 3 + 2], xr[2], s);
            }
            v = fmaxf(s, 0.f);
        }
        int idx = ((c1 * 10 + sh) * 36 + wi) * 2;
        y1d[idx] = v; y1d[idx + 1] = v;
    }
    __syncthreads();

    // ---- conv2: pack-free f32x2; both h-iterations share weight loads ----
    const int wg  = tid & 7;            // 4 w each
    const int c2g = (tid >> 3) & 7;     // 4 c2 each
    const int hg  = tid >> 6;           // h within strip: hg, hg+4
    const int c2  = c2g * 4;

    float acc[4][4];
#pragma unroll
    for (int a = 0; a < 4; ++a)
#pragma unroll
        for (int i = 0; i < 4; ++i) acc[a][i] = 0.f;

    const ull bb0 = *(const ull*)(b2s + c2);       // (c2, c2+1)
    const ull bb1 = *(const ull*)(b2s + c2 + 2);   // (c2+2, c2+3)

    ull y2p0[2][4], y2p1[2][4];
#pragma unroll
    for (int t = 0; t < 2; ++t)
#pragma unroll
        for (int i = 0; i < 4; ++i) { y2p0[t][i] = bb0; y2p1[t][i] = bb1; }

    for (int c1 = 0; c1 < 16; ++c1) {
        const float* ybase = y1d + (c1 * 360 + wg * 4) * 2;   // dup floats
        const float* wbase = w2s + c1 * 9 * 32 + c2;
#pragma unroll
        for (int dh = 0; dh < 3; ++dh) {
            ulonglong2 wq0 = *(const ulonglong2*)(wbase + (dh * 3 + 0) * 32);
            ulonglong2 wq1 = *(const ulonglong2*)(wbase + (dh * 3 + 1) * 32);
            ulonglong2 wq2 = *(const ulonglong2*)(wbase + (dh * 3 + 2) * 32);
#pragma unroll
            for (int t = 0; t < 2; ++t) {
                const int ho = hg + t * 4;
                const float* yr = ybase + (ho + dh) * 72;     // 16B aligned
                ulonglong2 ya = *(const ulonglong2*)(yr);
                ulonglong2 yb = *(const ulonglong2*)(yr + 4);
                ulonglong2 yc = *(const ulonglong2*)(yr + 8);
                ull rd0 = ya.x, rd1 = ya.y, rd2 = yb.x, rd3 = yb.y, rd4 = yc.x, rd5 = yc.y;
                // dw = 0 : rd0..rd3
                FMA_F32X2(y2p0[t][0], wq0.x, rd0, y2p0[t][0]);
                FMA_F32X2(y2p1[t][0], wq0.y, rd0, y2p1[t][0]);
                FMA_F32X2(y2p0[t][1], wq0.x, rd1, y2p0[t][1]);
                FMA_F32X2(y2p1[t][1], wq0.y, rd1, y2p1[t][1]);
                FMA_F32X2(y2p0[t][2], wq0.x, rd2, y2p0[t][2]);
                FMA_F32X2(y2p1[t][2], wq0.y, rd2, y2p1[t][2]);
                FMA_F32X2(y2p0[t][3], wq0.x, rd3, y2p0[t][3]);
                FMA_F32X2(y2p1[t][3], wq0.y, rd3, y2p1[t][3]);
                // dw = 1 : rd1..rd4
                FMA_F32X2(y2p0[t][0], wq1.x, rd1, y2p0[t][0]);
                FMA_F32X2(y2p1[t][0], wq1.y, rd1, y2p1[t][0]);
                FMA_F32X2(y2p0[t][1], wq1.x, rd2, y2p0[t][1]);
                FMA_F32X2(y2p1[t][1], wq1.y, rd2, y2p1[t][1]);
                FMA_F32X2(y2p0[t][2], wq1.x, rd3, y2p0[t][2]);
                FMA_F32X2(y2p1[t][2], wq1.y, rd3, y2p1[t][2]);
                FMA_F32X2(y2p0[t][3], wq1.x, rd4, y2p0[t][3]);
                FMA_F32X2(y2p1[t][3], wq1.y, rd4, y2p1[t][3]);
                // dw = 2 : rd2..rd5
                FMA_F32X2(y2p0[t][0], wq2.x, rd2, y2p0[t][0]);
                FMA_F32X2(y2p1[t][0], wq2.y, rd2, y2p1[t][0]);
                FMA_F32X2(y2p0[t][1], wq2.x, rd3, y2p0[t][1]);
                FMA_F32X2(y2p1[t][1], wq2.y, rd3, y2p1[t][1]);
                FMA_F32X2(y2p0[t][2], wq2.x, rd4, y2p0[t][2]);
                FMA_F32X2(y2p1[t][2], wq2.y, rd4, y2p1[t][2]);
                FMA_F32X2(y2p0[t][3], wq2.x, rd5, y2p0[t][3]);
                FMA_F32X2(y2p1[t][3], wq2.y, rd5, y2p1[t][3]);
            }
        }
    }
    // relu + accumulate over h (t)
#pragma unroll
    for (int t = 0; t < 2; ++t)
#pragma unroll
        for (int i = 0; i < 4; ++i) {
            float f0, f1, f2, f3;
            UNPACK2(f0, f1, y2p0[t][i]);
            UNPACK2(f2, f3, y2p1[t][i]);
            acc[0][i] += fmaxf(f0, 0.f);
            acc[1][i] += fmaxf(f1, 0.f);
            acc[2][i] += fmaxf(f2, 0.f);
            acc[3][i] += fmaxf(f3, 0.f);
        }

    // ---- c3 dot, fixed-order reduction ----
    const int gid = hg * 8 + c2g;       // 0..31
#pragma unroll
    for (int i = 0; i < 4; ++i) {
        float s = acc[0][i] * c3s[c2] + acc[1][i] * c3s[c2 + 1] +
                  acc[2][i] * c3s[c2 + 2] + acc[3][i] * c3s[c2 + 3];
        red[gid * 32 + wg * 4 + i] = s;
    }
    __syncthreads();
    if (tid < 32) {
        float s = 0.f;
        for (int g = 0; g < 32; ++g) s += red[g * 32 + tid];
        g_cpart[((blockIdx.y * 128 + n) * WW) + w0 + tid] = s;
    }
}

// ================= reduce conv strips =================
__global__ void k_red_tsp(const float* __restrict__ c3b) {
    int i = blockIdx.x * 256 + threadIdx.x;     // < 128*512
    if (i >= BB * HH * WW) return;
    int n = i / WW, w = i - n * WW;
    float s = 0.f;
#pragma unroll
    for (int st = 0; st < NSTRIP; ++st) s += g_cpart[(st * 128 + n) * WW + w];
    g_tsp[i] = s * (1.f / 64.f) + c3b[0];
}

// ================= top-k (64 of 512) + forced sink/local blocks =================
__global__ void k_topk() {
    const int bh = blockIdx.x;                    // 0..127
    __shared__ float v[WW];
    __shared__ unsigned char sel[WW];
    __shared__ float wv[8];
    __shared__ int   wix[8];
    const int tid = threadIdx.x;
    const int lane = tid & 31, wid = tid >> 5;

    for (int i = tid; i < WW; i += 256) { v[i] = g_tsp[bh * WW + i]; sel[i] = 0; }
    __syncthreads();

    for (int it = 0; it < NSEL; ++it) {
        float bv = v[tid]; int bi = tid;
        float b2 = v[tid + 256];
        if (b2 > bv) { bv = b2; bi = tid + 256; }
#pragma unroll
        for (int o = 16; o > 0; o >>= 1) {
            float ov = __shfl_xor_sync(0xffffffffu, bv, o);
            int   oi = __shfl_xor_sync(0xffffffffu, bi, o);
            if (ov > bv || (ov == bv && oi < bi)) { bv = ov; bi = oi; }
        }
        if (lane == 0) { wv[wid] = bv; wix[wid] = bi; }
        __syncthreads();
        if (tid == 0) {
            float m = wv[0]; int mi = wix[0];
#pragma unroll
            for (int g = 1; g < 8; ++g)
                if (wv[g] > m || (wv[g] == m && wix[g] < mi)) { m = wv[g]; mi = wix[g]; }
            sel[mi] = 1; v[mi] = -3.0e38f;
        }
        __syncthreads();
    }
    if (tid == 0) {
        for (int i = 0; i < 4; ++i) { sel[i] = 1; sel[WW - 4 + i] = 1; }
        int cnt = 0;
        for (int w = 0; w < WW; ++w)
            if (sel[w]) g_blist[bh * MAXBL + (cnt++)] = w;
        g_bcnt[bh] = cnt;
    }
}

// ================= sparse attention (one CTA per (b,h)) =================
__global__ void k_attn(const float* __restrict__ kc, const float* __restrict__ vc) {
    const int bh = blockIdx.x;
    const int b = bh >> 5, h = bh & 31, kvh = h >> 2;
    const int tid = threadIdx.x;                  // 256
    __shared__ float qs[DD];
    __shared__ float sc[MAXBL * BLK];
    __shared__ float redf[256];
    __shared__ float vacc[8][DD];

    const int cnt  = g_bcnt[bh];
    const int ntok = cnt * BLK;
    if (tid < DD) qs[tid] = g_q[(b * HH + h) * DD + tid];
    __syncthreads();

    const int wid = tid >> 5, lane = tid & 31;
    const float iscale = 0.08838834764831845f;    // 1/sqrt(128)
    const float4 q4 = *(const float4*)(qs + lane * 4);
    const size_t kvbase = (size_t)(b * KVH + kvh) * SC;

    for (int t = wid; t < ntok; t += 8) {
        int blk = g_blist[bh * MAXBL + (t >> 4)];
        int s = blk * BLK + (t & 15);
        const float* kr = (s == SS - 1)
            ? (g_kn + (b * KVH + kvh) * DD)
            : (kc + (kvbase + s) * DD);
        float4 k4 = ((const float4*)kr)[lane];
        float sum = fmaf(q4.x, k4.x, fmaf(q4.y, k4.y, fmaf(q4.z, k4.z, q4.w * k4.w)));
#pragma unroll
        for (int o = 16; o > 0; o >>= 1) sum += __shfl_xor_sync(0xffffffffu, sum, o);
        if (lane == 0) sc[t] = sum * iscale;
    }
    __syncthreads();

    float m = -3.0e38f;
    for (int t = tid; t < ntok; t += 256) m = fmaxf(m, sc[t]);
    redf[tid] = m; __syncthreads();
    for (int st = 128; st > 0; st >>= 1) {
        if (tid < st) redf[tid] = fmaxf(redf[tid], redf[tid + st]);
        __syncthreads();
    }
    m = redf[0];
    __syncthreads();

    float lp = 0.f;
    for (int t = tid; t < ntok; t += 256) { float p = expf(sc[t] - m); sc[t] = p; lp += p; }
    redf[tid] = lp; __syncthreads();
    for (int st = 128; st > 0; st >>= 1) {
        if (tid < st) redf[tid] += redf[tid + st];
        __syncthreads();
    }
    const float linv = 1.f / redf[0];
    __syncthreads();

    // V pass: all 8 warps accumulate partials, fixed-order combine
    float4 a4 = make_float4(0.f, 0.f, 0.f, 0.f);
    for (int t = wid; t < ntok; t += 8) {
        int blk = g_blist[bh * MAXBL + (t >> 4)];
        int s = blk * BLK + (t & 15);
        const float* vr = (s == SS - 1)
            ? (g_vn + (b * KVH + kvh) * DD)
            : (vc + (kvbase + s) * DD);
        float4 v4 = ((const float4*)vr)[lane];
        float p = sc[t];
        a4.x = fmaf(p, v4.x, a4.x);
        a4.y = fmaf(p, v4.y, a4.y);
        a4.z = fmaf(p, v4.z, a4.z);
        a4.w = fmaf(p, v4.w, a4.w);
    }
    *(float4*)(&vacc[wid][lane * 4]) = a4;
    __syncthreads();

    if (tid < DD) {
        float s = 0.f;
#pragma unroll
        for (int g = 0; g < 8; ++g) s += vacc[g][tid];
        g_ctx[b * HID + h * DD + tid] = s * linv;
    }
}

// ================= Wo GEMV =================
__global__ void k_out(const float* __restrict__ Wo) {
    __shared__ float cs[BB][512];
    const int ks = blockIdx.y;
    const int k0 = ks * 512;
    for (int i = threadIdx.x; i < BB * 512; i += 256) {
        int b = i >> 9, kk = i & 511;
        cs[b][kk] = g_ctx[b * HID + k0 + kk];
    }
    __syncthreads();
    const int c = blockIdx.x * 256 + threadIdx.x;
    float a0 = 0.f, a1 = 0.f, a2 = 0.f, a3 = 0.f;
    const float* p = Wo + (size_t)k0 * HID + c;
#pragma unroll 8
    for (int kk = 0; kk < 512; ++kk) {
        float w = p[(size_t)kk * HID];
        a0 = fmaf(cs[0][kk], w, a0);
        a1 = fmaf(cs[1][kk], w, a1);
        a2 = fmaf(cs[2][kk], w, a2);
        a3 = fmaf(cs[3][kk], w, a3);
    }
    g_opart[(ks * BB + 0) * HID + c] = a0;
    g_opart[(ks * BB + 1) * HID + c] = a1;
    g_opart[(ks * BB + 2) * HID + c] = a2;
    g_opart[(ks * BB + 3) * HID + c] = a3;
}

__global__ void k_red_out(float* __restrict__ out) {
    int i = blockIdx.x * 256 + threadIdx.x;
    if (i >= BB * HID) return;
    int b = i / HID, c = i - b * HID;
    float s = 0.f;
#pragma unroll
    for (int ks = 0; ks < KSPL; ++ks) s += g_opart[(ks * BB + b) * HID + c];
    out[i] = s;
}

// ================= host launcher =================
extern "C" void kernel_launch(void* const* d_in, const int* in_sizes, int n_in,
                              void* d_out, int out_size) {
    const float* hid  = (const float*)d_in[0];
    const float* kc   = (const float*)d_in[1];
    const float* vc   = (const float*)d_in[2];
    const float* hist = (const float*)d_in[3];
    const float* cosb = (const float*)d_in[4];
    const float* sinb = (const float*)d_in[5];
    const float* Wq   = (const float*)d_in[6];
    const float* Wk   = (const float*)d_in[7];
    const float* Wv   = (const float*)d_in[8];
    const float* Wo   = (const float*)d_in[9];
    const float* c1w  = (const float*)d_in[10];
    const float* c1b  = (const float*)d_in[11];
    const float* c2w  = (const float*)d_in[12];
    const float* c2b  = (const float*)d_in[13];
    const float* c3w  = (const float*)d_in[14];
    const float* c3b  = (const float*)d_in[15];
    float* out = (float*)d_out;

    cudaFuncSetAttribute(k_conv, cudaFuncAttributeMaxDynamicSharedMemorySize, CONV_SMEM_BYTES);

    k_qkv    <<<dim3(NCOL / 256, KSPL), 256>>>(hid, Wq, Wk, Wv);
    k_rope   <<<(BB * NCOL + 255) / 256, 256>>>(cosb, sinb);
    k_conv   <<<dim3(WW / 32, NSTRIP, BB * HH), 256, CONV_SMEM_BYTES>>>(hist, c1w, c1b, c2w, c2b, c3w, c3b);
    k_red_tsp<<<(BB * HH * WW + 255) / 256, 256>>>(c3b);
    k_topk   <<<BB * HH, 256>>>();
    k_attn   <<<BB * HH, 256>>>(kc, vc);
    k_out    <<<dim3(HID / 256, KSPL), 256>>>(Wo);
    k_red_out<<<(BB * HID + 255) / 256, 256>>>(out);
}

// round 4
// speedup vs baseline: 1.4246x; 1.4246x over previous
#include <cuda_runtime.h>
#include <math.h>
#include <stdint.h>

// ---------------- problem constants ----------------
#define BB    4
#define HH    32
#define KVH   8
#define DD    128
#define HID   4096
#define SC    8191          // cache length
#define SS    8192          // total sequence
#define WW    512           // blocks (S/BLK)
#define BLK   16
#define HIST  64
#define NSEL  64            // TOPK/BLK
#define MAXBL 80            // 64 topk + 8 forced, padded

#define KSPL  8             // k-splits for GEMVs
#define NCOL  (HID + 1024 + 1024)   // 6144 qkv columns

#define NSTRIP 8            // h-strips for conv
#define HSTR   8            // rows per strip

typedef unsigned long long ull;

// packed fp32x2 FMA (Blackwell): two exact IEEE fp32 FMAs per instruction
#define FMA_F32X2(d, a, b, c) \
    asm("fma.rn.f32x2 %0, %1, %2, %3;" : "=l"(d) : "l"(a), "l"(b), "l"(c))
#define PACK_DUP(d, x) \
    asm("mov.b64 %0, {%1, %2};" : "=l"(d) : "f"(x), "f"(x))
#define UNPACK2(lo, hi, q) \
    asm("mov.b64 {%0, %1}, %2;" : "=f"(lo), "=f"(hi) : "l"(q))

// ---------------- device scratch ----------------
__device__ float g_part [KSPL * BB * NCOL];          // qkv gemv partials
__device__ float g_q    [BB * HH * DD];              // roped q
__device__ float g_kn   [BB * KVH * DD];             // roped new k
__device__ float g_vn   [BB * KVH * DD];             // new v
__device__ float g_cpart[NSTRIP * BB * HH * WW];     // conv strip partials
__device__ int   g_blist[BB * HH * MAXBL];           // selected block lists
__device__ int   g_bcnt [BB * HH];
__device__ float g_ctx  [BB * HID];                  // attention output
__device__ float g_opart[KSPL * BB * HID];           // Wo gemv partials

// ================= QKV GEMV: partials =================
__global__ void k_qkv(const float* __restrict__ hid,
                      const float* __restrict__ Wq,
                      const float* __restrict__ Wk,
                      const float* __restrict__ Wv) {
    __shared__ float hs[BB][512];
    const int ks = blockIdx.y;
    const int k0 = ks * 512;
    for (int i = threadIdx.x; i < BB * 512; i += 256) {
        int b = i >> 9, kk = i & 511;
        hs[b][kk] = hid[b * HID + k0 + kk];
    }
    __syncthreads();

    const int c = blockIdx.x * 256 + threadIdx.x;   // 0..6143
    const float* Wm; int ld, cc;
    if (c < HID)              { Wm = Wq; ld = HID;  cc = c; }
    else if (c < HID + 1024)  { Wm = Wk; ld = 1024; cc = c - HID; }
    else                      { Wm = Wv; ld = 1024; cc = c - HID - 1024; }

    float a0 = 0.f, a1 = 0.f, a2 = 0.f, a3 = 0.f;
    const float* p = Wm + (size_t)k0 * ld + cc;
#pragma unroll 8
    for (int kk = 0; kk < 512; ++kk) {
        float w = p[(size_t)kk * ld];
        a0 = fmaf(hs[0][kk], w, a0);
        a1 = fmaf(hs[1][kk], w, a1);
        a2 = fmaf(hs[2][kk], w, a2);
        a3 = fmaf(hs[3][kk], w, a3);
    }
    g_part[((ks * BB + 0) * NCOL) + c] = a0;
    g_part[((ks * BB + 1) * NCOL) + c] = a1;
    g_part[((ks * BB + 2) * NCOL) + c] = a2;
    g_part[((ks * BB + 3) * NCOL) + c] = a3;
}

// ================= fused reduce + RoPE =================
__global__ void k_rope(const float* __restrict__ cosb, const float* __restrict__ sinb) {
    int i = blockIdx.x * 256 + threadIdx.x;      // < BB*NCOL
    if (i >= BB * NCOL) return;
    int b = i / NCOL, c = i - b * NCOL;
    float v = 0.f;
#pragma unroll
    for (int ks = 0; ks < KSPL; ++ks) v += g_part[(ks * BB + b) * NCOL + c];

    if (c < HID + 1024) {   // q or k : apply rope
        int d = c & (DD - 1);
        int pair = (d < DD / 2) ? c + DD / 2 : c - DD / 2;
        float pv = 0.f;
#pragma unroll
        for (int ks = 0; ks < KSPL; ++ks) pv += g_part[(ks * BB + b) * NCOL + pair];
        float cs = cosb[b * DD + d];
        float sn = sinb[b * DD + d];
        float rot = (d < DD / 2) ? -pv : pv;
        float out = v * cs + rot * sn;
        if (c < HID) g_q[b * HID + c] = out;
        else         g_kn[b * (KVH * DD) + (c - HID)] = out;
    } else {
        g_vn[b * (KVH * DD) + (c - HID - 1024)] = v;
    }
}

// ================= fused CNN, h-striped, f32x2 conv2 (R2-proven layout) ======
// static smem ~48.2KB, 3 CTAs/SM
__global__ void __launch_bounds__(256, 3)
k_conv(const float* __restrict__ hist,
       const float* __restrict__ c1w, const float* __restrict__ c1b,
       const float* __restrict__ c2w, const float* __restrict__ c2b,
       const float* __restrict__ c3w, const float* __restrict__ c3b) {
    __shared__ float y1s[16 * 10 * 36];   // conv1 out: [c1][sh 0..9][wi 0..35]
    __shared__ float sx [12 * 36];        // input strip with halo
    __shared__ float w2s[144 * 32];       // conv2 weights, k-major, c2 contiguous
    __shared__ float w1s[144];
    __shared__ float b1s[16];
    __shared__ float b2s[32];
    __shared__ float c3s[32];
    __shared__ float red[32 * 32];

    const int n   = blockIdx.z;            // image 0..127
    const int h0  = blockIdx.y * HSTR;     // strip base row
    const int w0  = blockIdx.x * 32;       // w tile base
    const int tid = threadIdx.x;

    // ---- load weights ----
    for (int i = tid; i < 144; i += 256) w1s[i] = c1w[i];
    if (tid < 16) b1s[tid] = c1b[tid];
    if (tid < 32) { b2s[tid] = c2b[tid]; c3s[tid] = c3w[tid]; }
    for (int i = tid; i < 32 * 144; i += 256) {
        int c2 = i & 31, kk = i >> 5;
        int c1 = kk / 9, r = kk - c1 * 9;
        w2s[kk * 32 + c2] = c2w[(c2 * 16 + c1) * 9 + r];
    }
    // ---- load x strip with halo, zero padded ----
    const float* xim = hist + (size_t)n * HIST * WW;
    for (int i = tid; i < 12 * 36; i += 256) {
        int sh = i / 36, sw = i - sh * 36;
        int h = h0 - 2 + sh, w = w0 - 2 + sw;
        float v = 0.f;
        if ((unsigned)h < 64u && (unsigned)w < 512u) v = xim[h * WW + w];
        sx[i] = v;
    }
    __syncthreads();

    // ---- conv1: rows sh 0..9 (hh = h0-1+sh), wi 0..33 ----
    for (int o = tid; o < 16 * 10 * 34; o += 256) {
        int c1 = o / 340;
        int r  = o - c1 * 340;
        int sh = r / 34;
        int wi = r - sh * 34;
        int hh = h0 - 1 + sh;
        int w  = w0 - 1 + wi;
        float v = 0.f;
        if ((unsigned)hh < 64u && (unsigned)w < 512u) {
            const float* wp = w1s + c1 * 9;
            float s = b1s[c1];
#pragma unroll
            for (int dh = 0; dh < 3; ++dh) {
                const float* xr = sx + (sh + dh) * 36 + wi;
                s = fmaf(wp[dh * 3 + 0], xr[0], s);
                s = fmaf(wp[dh * 3 + 1], xr[1], s);
                s = fmaf(wp[dh * 3 + 2], xr[2], s);
            }
            v = fmaxf(s, 0.f);
        }
        y1s[(c1 * 10 + sh) * 36 + wi] = v;
    }
    __syncthreads();

    // ---- conv2 with packed f32x2 (pairs over c2) ----
    const int wg  = tid & 7;            // 4 w each
    const int c2g = (tid >> 3) & 7;     // 4 c2 each
    const int hg  = tid >> 6;           // h within strip: hg, hg+4
    const int c2  = c2g * 4;

    float acc[4][4];
#pragma unroll
    for (int a = 0; a < 4; ++a)
#pragma unroll
        for (int i = 0; i < 4; ++i) acc[a][i] = 0.f;

    const ull bb0 = *(const ull*)(b2s + c2);       // (c2, c2+1)
    const ull bb1 = *(const ull*)(b2s + c2 + 2);   // (c2+2, c2+3)

#pragma unroll
    for (int t = 0; t < 2; ++t) {
        const int ho = hg + t * 4;      // output row within strip (0..7)
        ull y2p0[4], y2p1[4];
#pragma unroll
        for (int i = 0; i < 4; ++i) { y2p0[i] = bb0; y2p1[i] = bb1; }

        for (int c1 = 0; c1 < 16; ++c1) {
            const float* ybase = y1s + c1 * 360 + wg * 4;
            const float* wbase = w2s + c1 * 9 * 32 + c2;
#pragma unroll
            for (int dh = 0; dh < 3; ++dh) {
                const float* yr = ybase + (ho + dh) * 36;
                float4 ra = *(const float4*)(yr);
                float2 rb = *(const float2*)(yr + 4);
                ull rd[6];
                PACK_DUP(rd[0], ra.x); PACK_DUP(rd[1], ra.y);
                PACK_DUP(rd[2], ra.z); PACK_DUP(rd[3], ra.w);
                PACK_DUP(rd[4], rb.x); PACK_DUP(rd[5], rb.y);
#pragma unroll
                for (int dw = 0; dw < 3; ++dw) {
                    ulonglong2 wq = *(const ulonglong2*)(wbase + (dh * 3 + dw) * 32);
#pragma unroll
                    for (int i = 0; i < 4; ++i) {
                        FMA_F32X2(y2p0[i], wq.x, rd[i + dw], y2p0[i]);
                        FMA_F32X2(y2p1[i], wq.y, rd[i + dw], y2p1[i]);
                    }
                }
            }
        }
        // relu + accumulate over h
#pragma unroll
        for (int i = 0; i < 4; ++i) {
            float f0, f1, f2, f3;
            UNPACK2(f0, f1, y2p0[i]);
            UNPACK2(f2, f3, y2p1[i]);
            acc[0][i] += fmaxf(f0, 0.f);
            acc[1][i] += fmaxf(f1, 0.f);
            acc[2][i] += fmaxf(f2, 0.f);
            acc[3][i] += fmaxf(f3, 0.f);
        }
    }

    // ---- c3 dot, fixed-order reduction ----
    const int gid = hg * 8 + c2g;       // 0..31
#pragma unroll
    for (int i = 0; i < 4; ++i) {
        float s = acc[0][i] * c3s[c2] + acc[1][i] * c3s[c2 + 1] +
                  acc[2][i] * c3s[c2 + 2] + acc[3][i] * c3s[c2 + 3];
        red[gid * 32 + wg * 4 + i] = s;
    }
    __syncthreads();
    if (tid < 32) {
        float s = 0.f;
        for (int g = 0; g < 32; ++g) s += red[g * 32 + tid];
        g_cpart[((blockIdx.y * 128 + n) * WW) + w0 + tid] = s;
    }
}

// ===== top-k (64 of 512) with fused strip-reduce + forced sink/local blocks ====
__global__ void k_topk(const float* __restrict__ c3b) {
    const int bh = blockIdx.x;                    // 0..127
    __shared__ float v[WW];
    __shared__ unsigned char sel[WW];
    __shared__ float wv[8];
    __shared__ int   wix[8];
    const int tid = threadIdx.x;
    const int lane = tid & 31, wid = tid >> 5;
    const float bias = c3b[0];

    for (int i = tid; i < WW; i += 256) {
        float s = 0.f;
#pragma unroll
        for (int st = 0; st < NSTRIP; ++st) s += g_cpart[(st * 128 + bh) * WW + i];
        v[i] = s * (1.f / 64.f) + bias;
        sel[i] = 0;
    }
    __syncthreads();

    for (int it = 0; it < NSEL; ++it) {
        float bv = v[tid]; int bi = tid;
        float b2 = v[tid + 256];
        if (b2 > bv) { bv = b2; bi = tid + 256; }
#pragma unroll
        for (int o = 16; o > 0; o >>= 1) {
            float ov = __shfl_xor_sync(0xffffffffu, bv, o);
            int   oi = __shfl_xor_sync(0xffffffffu, bi, o);
            if (ov > bv || (ov == bv && oi < bi)) { bv = ov; bi = oi; }
        }
        if (lane == 0) { wv[wid] = bv; wix[wid] = bi; }
        __syncthreads();
        if (tid == 0) {
            float m = wv[0]; int mi = wix[0];
#pragma unroll
            for (int g = 1; g < 8; ++g)
                if (wv[g] > m || (wv[g] == m && wix[g] < mi)) { m = wv[g]; mi = wix[g]; }
            sel[mi] = 1; v[mi] = -3.0e38f;
        }
        __syncthreads();
    }
    if (tid == 0) {
        for (int i = 0; i < 4; ++i) { sel[i] = 1; sel[WW - 4 + i] = 1; }
        int cnt = 0;
        for (int w = 0; w < WW; ++w)
            if (sel[w]) g_blist[bh * MAXBL + (cnt++)] = w;
        g_bcnt[bh] = cnt;
    }
}

// ================= sparse attention (one CTA per (b,h)) =================
__global__ void k_attn(const float* __restrict__ kc, const float* __restrict__ vc) {
    const int bh = blockIdx.x;
    const int b = bh >> 5, h = bh & 31, kvh = h >> 2;
    const int tid = threadIdx.x;                  // 256
    __shared__ float qs[DD];
    __shared__ float sc[MAXBL * BLK];
    __shared__ float redf[256];
    __shared__ float vacc[8][DD];

    const int cnt  = g_bcnt[bh];
    const int ntok = cnt * BLK;
    if (tid < DD) qs[tid] = g_q[(b * HH + h) * DD + tid];
    __syncthreads();

    const int wid = tid >> 5, lane = tid & 31;
    const float iscale = 0.08838834764831845f;    // 1/sqrt(128)
    const float4 q4 = *(const float4*)(qs + lane * 4);
    const size_t kvbase = (size_t)(b * KVH + kvh) * SC;

    for (int t = wid; t < ntok; t += 8) {
        int blk = g_blist[bh * MAXBL + (t >> 4)];
        int s = blk * BLK + (t & 15);
        const float* kr = (s == SS - 1)
            ? (g_kn + (b * KVH + kvh) * DD)
            : (kc + (kvbase + s) * DD);
        float4 k4 = ((const float4*)kr)[lane];
        float sum = fmaf(q4.x, k4.x, fmaf(q4.y, k4.y, fmaf(q4.z, k4.z, q4.w * k4.w)));
#pragma unroll
        for (int o = 16; o > 0; o >>= 1) sum += __shfl_xor_sync(0xffffffffu, sum, o);
        if (lane == 0) sc[t] = sum * iscale;
    }
    __syncthreads();

    float m = -3.0e38f;
    for (int t = tid; t < ntok; t += 256) m = fmaxf(m, sc[t]);
    redf[tid] = m; __syncthreads();
    for (int st = 128; st > 0; st >>= 1) {
        if (tid < st) redf[tid] = fmaxf(redf[tid], redf[tid + st]);
        __syncthreads();
    }
    m = redf[0];
    __syncthreads();

    float lp = 0.f;
    for (int t = tid; t < ntok; t += 256) { float p = expf(sc[t] - m); sc[t] = p; lp += p; }
    redf[tid] = lp; __syncthreads();
    for (int st = 128; st > 0; st >>= 1) {
        if (tid < st) redf[tid] += redf[tid + st];
        __syncthreads();
    }
    const float linv = 1.f / redf[0];
    __syncthreads();

    // V pass: all 8 warps accumulate partials, fixed-order combine
    float4 a4 = make_float4(0.f, 0.f, 0.f, 0.f);
    for (int t = wid; t < ntok; t += 8) {
        int blk = g_blist[bh * MAXBL + (t >> 4)];
        int s = blk * BLK + (t & 15);
        const float* vr = (s == SS - 1)
            ? (g_vn + (b * KVH + kvh) * DD)
            : (vc + (kvbase + s) * DD);
        float4 v4 = ((const float4*)vr)[lane];
        float p = sc[t];
        a4.x = fmaf(p, v4.x, a4.x);
        a4.y = fmaf(p, v4.y, a4.y);
        a4.z = fmaf(p, v4.z, a4.z);
        a4.w = fmaf(p, v4.w, a4.w);
    }
    *(float4*)(&vacc[wid][lane * 4]) = a4;
    __syncthreads();

    if (tid < DD) {
        float s = 0.f;
#pragma unroll
        for (int g = 0; g < 8; ++g) s += vacc[g][tid];
        g_ctx[b * HID + h * DD + tid] = s * linv;
    }
}

// ================= Wo GEMV =================
__global__ void k_out(const float* __restrict__ Wo) {
    __shared__ float cs[BB][512];
    const int ks = blockIdx.y;
    const int k0 = ks * 512;
    for (int i = threadIdx.x; i < BB * 512; i += 256) {
        int b = i >> 9, kk = i & 511;
        cs[b][kk] = g_ctx[b * HID + k0 + kk];
    }
    __syncthreads();
    const int c = blockIdx.x * 256 + threadIdx.x;
    float a0 = 0.f, a1 = 0.f, a2 = 0.f, a3 = 0.f;
    const float* p = Wo + (size_t)k0 * HID + c;
#pragma unroll 8
    for (int kk = 0; kk < 512; ++kk) {
        float w = p[(size_t)kk * HID];
        a0 = fmaf(cs[0][kk], w, a0);
        a1 = fmaf(cs[1][kk], w, a1);
        a2 = fmaf(cs[2][kk], w, a2);
        a3 = fmaf(cs[3][kk], w, a3);
    }
    g_opart[(ks * BB + 0) * HID + c] = a0;
    g_opart[(ks * BB + 1) * HID + c] = a1;
    g_opart[(ks * BB + 2) * HID + c] = a2;
    g_opart[(ks * BB + 3) * HID + c] = a3;
}

__global__ void k_red_out(float* __restrict__ out) {
    int i = blockIdx.x * 256 + threadIdx.x;
    if (i >= BB * HID) return;
    int b = i / HID, c = i - b * HID;
    float s = 0.f;
#pragma unroll
    for (int ks = 0; ks < KSPL; ++ks) s += g_opart[(ks * BB + b) * HID + c];
    out[i] = s;
}

// ================= host launcher =================
extern "C" void kernel_launch(void* const* d_in, const int* in_sizes, int n_in,
                              void* d_out, int out_size) {
    const float* hid  = (const float*)d_in[0];
    const float* kc   = (const float*)d_in[1];
    const float* vc   = (const float*)d_in[2];
    const float* hist = (const float*)d_in[3];
    const float* cosb = (const float*)d_in[4];
    const float* sinb = (const float*)d_in[5];
    const float* Wq   = (const float*)d_in[6];
    const float* Wk   = (const float*)d_in[7];
    const float* Wv   = (const float*)d_in[8];
    const float* Wo   = (const float*)d_in[9];
    const float* c1w  = (const float*)d_in[10];
    const float* c1b  = (const float*)d_in[11];
    const float* c2w  = (const float*)d_in[12];
    const float* c2b  = (const float*)d_in[13];
    const float* c3w  = (const float*)d_in[14];
    const float* c3b  = (const float*)d_in[15];
    float* out = (float*)d_out;

    k_qkv    <<<dim3(NCOL / 256, KSPL), 256>>>(hid, Wq, Wk, Wv);
    k_rope   <<<(BB * NCOL + 255) / 256, 256>>>(cosb, sinb);
    k_conv   <<<dim3(WW / 32, NSTRIP, BB * HH), 256>>>(hist, c1w, c1b, c2w, c2b, c3w, c3b);
    k_topk   <<<BB * HH, 256>>>(c3b);
    k_attn   <<<BB * HH, 256>>>(kc, vc);
    k_out    <<<dim3(HID / 256, KSPL), 256>>>(Wo);
    k_red_out<<<(BB * HID + 255) / 256, 256>>>(out);
}